// round 7
// baseline (speedup 1.0000x reference)
#include <cuda_runtime.h>
#include <cuda_bf16.h>
#include <math.h>
#include <stdint.h>

#define N_ELEM 131072
#define C_DIM  512
#define G_DIM  4096
#define NOUT   1024     // Wf cols || Wg cols

// ---------------- scratch (device globals; no allocation allowed) ----------------
__device__ __nv_bfloat16 g_whi[(size_t)NOUT * C_DIM];     // 1 MB, K-major [n][k]
__device__ __nv_bfloat16 g_wlo[(size_t)NOUT * C_DIM];     // 1 MB
__device__ float g_eg[(size_t)N_ELEM * C_DIM];            // 256 MB
__device__ float g_denom[G_DIM * C_DIM];                  // 8 MB
__device__ float g_y[G_DIM * C_DIM];                      // 8 MB
__device__ float g_yh[G_DIM * C_DIM];                     // 8 MB

#define MMA16816(d, a0, a1, a2, a3, b0, b1) \
    asm volatile("mma.sync.aligned.m16n8k16.row.col.f32.bf16.bf16.f32 " \
                 "{%0,%1,%2,%3}, {%4,%5,%6,%7}, {%8,%9}, {%0,%1,%2,%3};" \
                 : "+f"((d)[0]), "+f"((d)[1]), "+f"((d)[2]), "+f"((d)[3]) \
                 : "r"(a0), "r"(a1), "r"(a2), "r"(a3), "r"(b0), "r"(b1))

__device__ __forceinline__ uint32_t smem_u32(const void* p) {
    uint32_t a;
    asm("{ .reg .u64 t; cvta.to.shared.u64 t, %1; cvt.u32.u64 %0, t; }" : "=r"(a) : "l"(p));
    return a;
}
__device__ __forceinline__ void cp16(uint32_t saddr, const void* g) {
    asm volatile("cp.async.cg.shared.global [%0], [%1], 16;" :: "r"(saddr), "l"(g));
}

// ---------------- zero accumulators ----------------
__global__ void zero_kernel() {
    int i = blockIdx.x * blockDim.x + threadIdx.x;   // G*C/4
    float4 z = make_float4(0.f, 0.f, 0.f, 0.f);
    ((float4*)g_denom)[i] = z;
    ((float4*)g_y)[i] = z;
}

// ---------------- build Whi/Wlo [n=1024][k=512] K-major bf16 ----------------
__global__ void build_w_kernel(const float* __restrict__ Wf,
                               const float* __restrict__ Wg) {
    int i = blockIdx.x * blockDim.x + threadIdx.x;   // NOUT*C_DIM
    int n = i >> 9;
    int k = i & 511;
    const float* W = (n < 512) ? Wf : Wg;
    float w = W[(size_t)k * C_DIM + (n & 511)];
    __nv_bfloat16 hi = __float2bfloat16(w);
    g_whi[i] = hi;
    g_wlo[i] = __float2bfloat16(w - __bfloat162float(hi));
}

// ---------------- mma.sync bf16-split GEMM halves ------------------------------
// Mainloop identical to verified R6: A (x fp32) read once per k-chunk, split
// hi/lo in regs; 3 MMA passes hi*Whi + hi*Wlo + lo*Whi per chunk.
// IS_G=true : eg = exp(x Wg + bg) -> store g_eg, atomics into g_denom.
// IS_G=false: fx = x Wf + bf in regs -> read eg/denom, atomicAdd y += fx*eg/den.
#define SPITCH 40
#define TILE_E (128 * SPITCH)        // bf16 elems per tile (10240 B)
#define STG_E  (4 * TILE_E)          // elems per stage (4 tiles)

template <bool IS_G>
__global__ __launch_bounds__(256, 1)
void gemm_half(const float* __restrict__ x, const int* __restrict__ ix,
               const float* __restrict__ bias) {
    extern __shared__ __nv_bfloat16 sm[];
    // stage s: [AHI, ALO, BHI, BLO], each 128 x SPITCH

    const int tid  = threadIdx.x;
    const int l    = tid & 31;
    const int warp = tid >> 5;
    const int bx   = blockIdx.x;          // 0..3 -> 128-col stripe of this half
    const int row0 = blockIdx.y * 128;
    const int n0g  = (IS_G ? 512 : 0) + bx * 128;

    const int wm = warp >> 2;             // 0..1
    const int wn = warp & 3;              // 0..3
    const int m_base = wm * 64;
    const int n_base = wn * 32;
    const int gid = l >> 2, tig = l & 3;

    float acc[4][4][4];
#pragma unroll
    for (int t = 0; t < 4; t++)
#pragma unroll
        for (int n = 0; n < 4; n++)
#pragma unroll
            for (int r = 0; r < 4; r++) acc[t][n][r] = 0.f;

    float4 stg[4];

#define LOAD_A(CH) do {                                                       \
        const int kc_ = (CH) * 32;                                            \
        _Pragma("unroll")                                                     \
        for (int i_ = 0; i_ < 4; i_++) {                                      \
            int u_ = tid + i_ * 256;                                          \
            int r_ = u_ >> 3, s_ = u_ & 7;                                    \
            stg[i_] = *(const float4*)(x + (size_t)(row0 + r_) * C_DIM + kc_ + s_ * 4); \
        }                                                                     \
    } while (0)

#define STORE_A(BUF) do {                                                     \
        __nv_bfloat16* ahi_ = sm + (BUF) * STG_E;                             \
        __nv_bfloat16* alo_ = ahi_ + TILE_E;                                  \
        _Pragma("unroll")                                                     \
        for (int i_ = 0; i_ < 4; i_++) {                                      \
            int u_ = tid + i_ * 256;                                          \
            int r_ = u_ >> 3, s_ = u_ & 7;                                    \
            float4 v_ = stg[i_];                                              \
            __nv_bfloat162 h01_, h23_, l01_, l23_;                            \
            h01_.x = __float2bfloat16(v_.x); h01_.y = __float2bfloat16(v_.y); \
            h23_.x = __float2bfloat16(v_.z); h23_.y = __float2bfloat16(v_.w); \
            l01_.x = __float2bfloat16(v_.x - __bfloat162float(h01_.x));       \
            l01_.y = __float2bfloat16(v_.y - __bfloat162float(h01_.y));       \
            l23_.x = __float2bfloat16(v_.z - __bfloat162float(h23_.x));       \
            l23_.y = __float2bfloat16(v_.w - __bfloat162float(h23_.y));       \
            uint2 H_, L_;                                                     \
            H_.x = *(uint32_t*)&h01_; H_.y = *(uint32_t*)&h23_;               \
            L_.x = *(uint32_t*)&l01_; L_.y = *(uint32_t*)&l23_;               \
            *(uint2*)(ahi_ + r_ * SPITCH + s_ * 4) = H_;                      \
            *(uint2*)(alo_ + r_ * SPITCH + s_ * 4) = L_;                      \
        }                                                                     \
    } while (0)

#define LOAD_B(BUF, CH) do {                                                  \
        const int kc_ = (CH) * 32;                                            \
        uint32_t bhi_ = smem_u32(sm + (BUF) * STG_E + 2 * TILE_E);            \
        uint32_t blo_ = bhi_ + TILE_E * 2;                                    \
        _Pragma("unroll")                                                     \
        for (int i_ = 0; i_ < 2; i_++) {                                      \
            int u_ = tid + i_ * 256;                                          \
            int nr_ = u_ >> 2, ch_ = u_ & 3;                                  \
            size_t go_ = (size_t)(n0g + nr_) * C_DIM + kc_ + ch_ * 8;         \
            uint32_t so_ = nr_ * (SPITCH * 2) + ch_ * 16;                     \
            cp16(bhi_ + so_, g_whi + go_);                                    \
            cp16(blo_ + so_, g_wlo + go_);                                    \
        }                                                                     \
        asm volatile("cp.async.commit_group;" ::: "memory");                  \
    } while (0)

    LOAD_B(0, 0);
    LOAD_A(0);
    STORE_A(0);
    asm volatile("cp.async.wait_group 0;" ::: "memory");
    __syncthreads();

    for (int it = 0; it < 16; it++) {
        const int cur = it & 1;
        if (it + 1 < 16) {
            LOAD_B(cur ^ 1, it + 1);
            LOAD_A(it + 1);
        }

        const __nv_bfloat16* Ahi = sm + cur * STG_E;
        const __nv_bfloat16* Alo = Ahi + TILE_E;
        const __nv_bfloat16* Bhi = Ahi + 2 * TILE_E;
        const __nv_bfloat16* Blo = Ahi + 3 * TILE_E;

#pragma unroll
        for (int s = 0; s < 2; s++) {
            const int k0 = s * 16 + 2 * tig;
            uint32_t aH[4][4], aL[4][4];
#pragma unroll
            for (int t = 0; t < 4; t++) {
                const int r = m_base + t * 16 + gid;
                aH[t][0] = *(const uint32_t*)(Ahi + r * SPITCH + k0);
                aH[t][1] = *(const uint32_t*)(Ahi + (r + 8) * SPITCH + k0);
                aH[t][2] = *(const uint32_t*)(Ahi + r * SPITCH + k0 + 8);
                aH[t][3] = *(const uint32_t*)(Ahi + (r + 8) * SPITCH + k0 + 8);
                aL[t][0] = *(const uint32_t*)(Alo + r * SPITCH + k0);
                aL[t][1] = *(const uint32_t*)(Alo + (r + 8) * SPITCH + k0);
                aL[t][2] = *(const uint32_t*)(Alo + r * SPITCH + k0 + 8);
                aL[t][3] = *(const uint32_t*)(Alo + (r + 8) * SPITCH + k0 + 8);
            }
            uint32_t bH[4][2], bL[4][2];
#pragma unroll
            for (int nt = 0; nt < 4; nt++) {
                const int rn = n_base + nt * 8 + gid;
                bH[nt][0] = *(const uint32_t*)(Bhi + rn * SPITCH + k0);
                bH[nt][1] = *(const uint32_t*)(Bhi + rn * SPITCH + k0 + 8);
                bL[nt][0] = *(const uint32_t*)(Blo + rn * SPITCH + k0);
                bL[nt][1] = *(const uint32_t*)(Blo + rn * SPITCH + k0 + 8);
            }
#pragma unroll
            for (int t = 0; t < 4; t++)
#pragma unroll
                for (int nt = 0; nt < 4; nt++) {
                    MMA16816(acc[t][nt], aH[t][0], aH[t][1], aH[t][2], aH[t][3],
                             bH[nt][0], bH[nt][1]);
                    MMA16816(acc[t][nt], aH[t][0], aH[t][1], aH[t][2], aH[t][3],
                             bL[nt][0], bL[nt][1]);
                    MMA16816(acc[t][nt], aL[t][0], aL[t][1], aL[t][2], aL[t][3],
                             bH[nt][0], bH[nt][1]);
                }
        }

        if (it + 1 < 16) {
            STORE_A(cur ^ 1);
            asm volatile("cp.async.wait_group 0;" ::: "memory");
        }
        __syncthreads();
    }
#undef LOAD_A
#undef STORE_A
#undef LOAD_B

    // ---- epilogue ----
#pragma unroll
    for (int t = 0; t < 4; t++) {
#pragma unroll
        for (int h = 0; h < 2; h++) {
            const int m = row0 + m_base + t * 16 + gid + h * 8;
            const int grp = ix[m];
#pragma unroll
            for (int nt = 0; nt < 4; nt++) {
                const int cg = n0g + n_base + nt * 8 + 2 * tig;
                const int cw = cg & 511;
                float v0 = acc[t][nt][2 * h]     + bias[cw];
                float v1 = acc[t][nt][2 * h + 1] + bias[cw + 1];
                if (IS_G) {
                    v0 = expf(v0);
                    v1 = expf(v1);
                    *(float2*)&g_eg[(size_t)m * C_DIM + cw] = make_float2(v0, v1);
                    float* dp = &g_denom[(size_t)grp * C_DIM + cw];
                    atomicAdd(dp,     v0);
                    atomicAdd(dp + 1, v1);
                } else {
                    float2 e = *(const float2*)&g_eg[(size_t)m * C_DIM + cw];
                    float2 d = *(const float2*)&g_denom[(size_t)grp * C_DIM + cw];
                    float* yp = &g_y[(size_t)grp * C_DIM + cw];
                    atomicAdd(yp,     v0 * (e.x / d.x));
                    atomicAdd(yp + 1, v1 * (e.y / d.y));
                }
            }
        }
    }
}

// ---------------- yh = y @ Wh + bh (fp32 SIMT, small) ----------------
__global__ __launch_bounds__(256, 2)
void gemm_h_kernel(const float* __restrict__ Wh, const float* __restrict__ bh)
{
    constexpr int BM = 128, BN = 128, BK = 16;
    __shared__ float As[BK][BM];
    __shared__ float Bs[BK][BN];

    const int tid  = threadIdx.x;
    const int col0 = blockIdx.x * BN;
    const int row0 = blockIdx.y * BM;
    const int ty = tid >> 4, tx = tid & 15;
    const int trow = ty * 8, tcol = tx * 8;

    float acc[8][8];
#pragma unroll
    for (int i = 0; i < 8; i++)
#pragma unroll
        for (int j = 0; j < 8; j++) acc[i][j] = 0.f;

    for (int k0 = 0; k0 < C_DIM; k0 += BK) {
#pragma unroll
        for (int s = 0; s < 2; s++) {
            int ll = tid + s * 256;
            int ar  = ll >> 2;
            int akq = (ll & 3) * 4;
            float4 av = *(const float4*)&g_y[(size_t)(row0 + ar) * C_DIM + k0 + akq];
            As[akq + 0][ar] = av.x;
            As[akq + 1][ar] = av.y;
            As[akq + 2][ar] = av.z;
            As[akq + 3][ar] = av.w;
            int bk  = ll >> 5;
            int bcq = (ll & 31) * 4;
            float4 bv = *(const float4*)&Wh[(size_t)(k0 + bk) * C_DIM + col0 + bcq];
            *(float4*)&Bs[bk][bcq] = bv;
        }
        __syncthreads();
#pragma unroll
        for (int k = 0; k < BK; k++) {
            float a[8], b[8];
#pragma unroll
            for (int i = 0; i < 8; i++) a[i] = As[k][trow + i];
#pragma unroll
            for (int j = 0; j < 8; j++) b[j] = Bs[k][tcol + j];
#pragma unroll
            for (int i = 0; i < 8; i++)
#pragma unroll
                for (int j = 0; j < 8; j++)
                    acc[i][j] = fmaf(a[i], b[j], acc[i][j]);
        }
        __syncthreads();
    }

    float bv[8];
#pragma unroll
    for (int j = 0; j < 8; j++) bv[j] = bh[col0 + tcol + j];
#pragma unroll
    for (int i = 0; i < 8; i++) {
        size_t off = (size_t)(row0 + trow + i) * C_DIM + col0 + tcol;
        *(float4*)&g_yh[off]     = make_float4(acc[i][0] + bv[0], acc[i][1] + bv[1],
                                               acc[i][2] + bv[2], acc[i][3] + bv[3]);
        *(float4*)&g_yh[off + 4] = make_float4(acc[i][4] + bv[4], acc[i][5] + bv[5],
                                               acc[i][6] + bv[6], acc[i][7] + bv[7]);
    }
}

// ---------------- out[n] = yh[ix[n]] ----------------
__global__ void gather_kernel(const int* __restrict__ ix, float* __restrict__ out) {
    size_t idx = (size_t)blockIdx.x * blockDim.x + threadIdx.x;  // N*C/4
    int n  = (int)(idx >> 7);
    int cq = (int)(idx & 127) << 2;
    int g  = ix[n];
    *(float4*)&out[((size_t)n << 9) + cq] = *(const float4*)&g_yh[((size_t)g << 9) + cq];
}

extern "C" void kernel_launch(void* const* d_in, const int* in_sizes, int n_in,
                              void* d_out, int out_size) {
    const float* x  = (const float*)d_in[0];
    const int*   ix = (const int*)d_in[1];
    const float* Wf = (const float*)d_in[2];
    const float* bf = (const float*)d_in[3];
    const float* Wg = (const float*)d_in[4];
    const float* bg = (const float*)d_in[5];
    const float* Wh = (const float*)d_in[6];
    const float* bh = (const float*)d_in[7];
    float* out = (float*)d_out;

    const int SMEM = 2 * 4 * TILE_E * 2;   // 81920 bytes
    cudaFuncSetAttribute(gemm_half<true>,  cudaFuncAttributeMaxDynamicSharedMemorySize, SMEM);
    cudaFuncSetAttribute(gemm_half<false>, cudaFuncAttributeMaxDynamicSharedMemorySize, SMEM);

    zero_kernel<<<(G_DIM * C_DIM / 4) / 256, 256>>>();
    build_w_kernel<<<(NOUT * C_DIM) / 256, 256>>>(Wf, Wg);

    dim3 g1(4, N_ELEM / 128);
    gemm_half<true><<<g1, 256, SMEM>>>(x, ix, bg);    // eg + denom
    gemm_half<false><<<g1, 256, SMEM>>>(x, ix, bf);   // fx, fused aggregation

    dim3 g2(C_DIM / 128, G_DIM / 128);
    gemm_h_kernel<<<g2, 256>>>(Wh, bh);

    gather_kernel<<<(N_ELEM * (C_DIM / 4)) / 256, 256>>>(ix, out);
}

// round 8
// speedup vs baseline: 1.2725x; 1.2725x over previous
#include <cuda_runtime.h>
#include <cuda_bf16.h>
#include <math.h>
#include <stdint.h>

#define N_ELEM 131072
#define C_DIM  512
#define G_DIM  4096
#define NOUT   1024     // Wf cols || Wg cols

// ---------------- scratch (device globals; no allocation allowed) ----------------
__device__ __nv_bfloat16 g_whi[(size_t)NOUT * C_DIM];     // 1 MB, K-major [n][k]
__device__ __nv_bfloat16 g_wlo[(size_t)NOUT * C_DIM];     // 1 MB
__device__ float g_eg[(size_t)N_ELEM * C_DIM];            // 256 MB
__device__ float g_denom[G_DIM * C_DIM];                  // 8 MB
__device__ float g_y[G_DIM * C_DIM];                      // 8 MB
__device__ float g_yh[G_DIM * C_DIM];                     // 8 MB

#define MMA16816(d, a0, a1, a2, a3, b0, b1) \
    asm volatile("mma.sync.aligned.m16n8k16.row.col.f32.bf16.bf16.f32 " \
                 "{%0,%1,%2,%3}, {%4,%5,%6,%7}, {%8,%9}, {%0,%1,%2,%3};" \
                 : "+f"((d)[0]), "+f"((d)[1]), "+f"((d)[2]), "+f"((d)[3]) \
                 : "r"(a0), "r"(a1), "r"(a2), "r"(a3), "r"(b0), "r"(b1))

__device__ __forceinline__ uint32_t smem_u32(const void* p) {
    uint32_t a;
    asm("{ .reg .u64 t; cvta.to.shared.u64 t, %1; cvt.u32.u64 %0, t; }" : "=r"(a) : "l"(p));
    return a;
}
__device__ __forceinline__ void cp16(uint32_t saddr, const void* g) {
    asm volatile("cp.async.cg.shared.global [%0], [%1], 16;" :: "r"(saddr), "l"(g));
}

// ---------------- zero accumulators ----------------
__global__ void zero_kernel() {
    int i = blockIdx.x * blockDim.x + threadIdx.x;   // G*C/4
    float4 z = make_float4(0.f, 0.f, 0.f, 0.f);
    ((float4*)g_denom)[i] = z;
    ((float4*)g_y)[i] = z;
}

// ---------------- build Whi/Wlo [n=1024][k=512] K-major bf16 ----------------
__global__ void build_w_kernel(const float* __restrict__ Wf,
                               const float* __restrict__ Wg) {
    int i = blockIdx.x * blockDim.x + threadIdx.x;   // NOUT*C_DIM
    int n = i >> 9;
    int k = i & 511;
    const float* W = (n < 512) ? Wf : Wg;
    float w = W[(size_t)k * C_DIM + (n & 511)];
    __nv_bfloat16 hi = __float2bfloat16(w);
    g_whi[i] = hi;
    g_wlo[i] = __float2bfloat16(w - __bfloat162float(hi));
}

// ---------------- mma.sync bf16-split GEMM halves ------------------------------
// Mainloop as verified in R6/R7; inner fragment loop restructured so only one
// m-tile's A fragments are live at a time -> fits 128 regs -> 2 CTAs/SM.
// IS_G=true : eg = exp(x Wg + bg) -> store g_eg, atomics into g_denom.
// IS_G=false: fx = x Wf + bf in regs -> read eg/denom, atomicAdd y += fx*eg/den.
#define SPITCH 40
#define TILE_E (128 * SPITCH)        // bf16 elems per tile (10240 B)
#define STG_E  (4 * TILE_E)          // elems per stage (4 tiles)

template <bool IS_G>
__global__ __launch_bounds__(256, 2)
void gemm_half(const float* __restrict__ x, const int* __restrict__ ix,
               const float* __restrict__ bias) {
    extern __shared__ __nv_bfloat16 sm[];
    // stage s: [AHI, ALO, BHI, BLO], each 128 x SPITCH

    const int tid  = threadIdx.x;
    const int l    = tid & 31;
    const int warp = tid >> 5;
    const int bx   = blockIdx.x;          // 0..3 -> 128-col stripe of this half
    const int row0 = blockIdx.y * 128;
    const int n0g  = (IS_G ? 512 : 0) + bx * 128;

    const int wm = warp >> 2;             // 0..1
    const int wn = warp & 3;              // 0..3
    const int m_base = wm * 64;
    const int n_base = wn * 32;
    const int gid = l >> 2, tig = l & 3;

    float acc[4][4][4];
#pragma unroll
    for (int t = 0; t < 4; t++)
#pragma unroll
        for (int n = 0; n < 4; n++)
#pragma unroll
            for (int r = 0; r < 4; r++) acc[t][n][r] = 0.f;

    float4 stg[4];

#define LOAD_A(CH) do {                                                       \
        const int kc_ = (CH) * 32;                                            \
        _Pragma("unroll")                                                     \
        for (int i_ = 0; i_ < 4; i_++) {                                      \
            int u_ = tid + i_ * 256;                                          \
            int r_ = u_ >> 3, s_ = u_ & 7;                                    \
            stg[i_] = *(const float4*)(x + (size_t)(row0 + r_) * C_DIM + kc_ + s_ * 4); \
        }                                                                     \
    } while (0)

#define STORE_A(BUF) do {                                                     \
        __nv_bfloat16* ahi_ = sm + (BUF) * STG_E;                             \
        __nv_bfloat16* alo_ = ahi_ + TILE_E;                                  \
        _Pragma("unroll")                                                     \
        for (int i_ = 0; i_ < 4; i_++) {                                      \
            int u_ = tid + i_ * 256;                                          \
            int r_ = u_ >> 3, s_ = u_ & 7;                                    \
            float4 v_ = stg[i_];                                              \
            __nv_bfloat162 h01_, h23_, l01_, l23_;                            \
            h01_.x = __float2bfloat16(v_.x); h01_.y = __float2bfloat16(v_.y); \
            h23_.x = __float2bfloat16(v_.z); h23_.y = __float2bfloat16(v_.w); \
            l01_.x = __float2bfloat16(v_.x - __bfloat162float(h01_.x));       \
            l01_.y = __float2bfloat16(v_.y - __bfloat162float(h01_.y));       \
            l23_.x = __float2bfloat16(v_.z - __bfloat162float(h23_.x));       \
            l23_.y = __float2bfloat16(v_.w - __bfloat162float(h23_.y));       \
            uint2 H_, L_;                                                     \
            H_.x = *(uint32_t*)&h01_; H_.y = *(uint32_t*)&h23_;               \
            L_.x = *(uint32_t*)&l01_; L_.y = *(uint32_t*)&l23_;               \
            *(uint2*)(ahi_ + r_ * SPITCH + s_ * 4) = H_;                      \
            *(uint2*)(alo_ + r_ * SPITCH + s_ * 4) = L_;                      \
        }                                                                     \
    } while (0)

#define LOAD_B(BUF, CH) do {                                                  \
        const int kc_ = (CH) * 32;                                            \
        uint32_t bhi_ = smem_u32(sm + (BUF) * STG_E + 2 * TILE_E);            \
        uint32_t blo_ = bhi_ + TILE_E * 2;                                    \
        _Pragma("unroll")                                                     \
        for (int i_ = 0; i_ < 2; i_++) {                                      \
            int u_ = tid + i_ * 256;                                          \
            int nr_ = u_ >> 2, ch_ = u_ & 3;                                  \
            size_t go_ = (size_t)(n0g + nr_) * C_DIM + kc_ + ch_ * 8;         \
            uint32_t so_ = nr_ * (SPITCH * 2) + ch_ * 16;                     \
            cp16(bhi_ + so_, g_whi + go_);                                    \
            cp16(blo_ + so_, g_wlo + go_);                                    \
        }                                                                     \
        asm volatile("cp.async.commit_group;" ::: "memory");                  \
    } while (0)

    LOAD_B(0, 0);
    LOAD_A(0);
    STORE_A(0);
    asm volatile("cp.async.wait_group 0;" ::: "memory");
    __syncthreads();

    for (int it = 0; it < 16; it++) {
        const int cur = it & 1;
        if (it + 1 < 16) {
            LOAD_B(cur ^ 1, it + 1);
            LOAD_A(it + 1);
        }

        const __nv_bfloat16* Ahi = sm + cur * STG_E;
        const __nv_bfloat16* Alo = Ahi + TILE_E;
        const __nv_bfloat16* Bhi = Ahi + 2 * TILE_E;
        const __nv_bfloat16* Blo = Ahi + 3 * TILE_E;

#pragma unroll
        for (int s = 0; s < 2; s++) {
            const int k0 = s * 16 + 2 * tig;
            uint32_t bH[4][2], bL[4][2];
#pragma unroll
            for (int nt = 0; nt < 4; nt++) {
                const int rn = n_base + nt * 8 + gid;
                bH[nt][0] = *(const uint32_t*)(Bhi + rn * SPITCH + k0);
                bH[nt][1] = *(const uint32_t*)(Bhi + rn * SPITCH + k0 + 8);
                bL[nt][0] = *(const uint32_t*)(Blo + rn * SPITCH + k0);
                bL[nt][1] = *(const uint32_t*)(Blo + rn * SPITCH + k0 + 8);
            }
#pragma unroll
            for (int t = 0; t < 4; t++) {
                const int r = m_base + t * 16 + gid;
                uint32_t aH[4], aL[4];
                aH[0] = *(const uint32_t*)(Ahi + r * SPITCH + k0);
                aH[1] = *(const uint32_t*)(Ahi + (r + 8) * SPITCH + k0);
                aH[2] = *(const uint32_t*)(Ahi + r * SPITCH + k0 + 8);
                aH[3] = *(const uint32_t*)(Ahi + (r + 8) * SPITCH + k0 + 8);
                aL[0] = *(const uint32_t*)(Alo + r * SPITCH + k0);
                aL[1] = *(const uint32_t*)(Alo + (r + 8) * SPITCH + k0);
                aL[2] = *(const uint32_t*)(Alo + r * SPITCH + k0 + 8);
                aL[3] = *(const uint32_t*)(Alo + (r + 8) * SPITCH + k0 + 8);
#pragma unroll
                for (int nt = 0; nt < 4; nt++) {
                    MMA16816(acc[t][nt], aH[0], aH[1], aH[2], aH[3],
                             bH[nt][0], bH[nt][1]);
                    MMA16816(acc[t][nt], aH[0], aH[1], aH[2], aH[3],
                             bL[nt][0], bL[nt][1]);
                    MMA16816(acc[t][nt], aL[0], aL[1], aL[2], aL[3],
                             bH[nt][0], bH[nt][1]);
                }
            }
        }

        if (it + 1 < 16) {
            STORE_A(cur ^ 1);
            asm volatile("cp.async.wait_group 0;" ::: "memory");
        }
        __syncthreads();
    }
#undef LOAD_A
#undef STORE_A
#undef LOAD_B

    // ---- epilogue ----
#pragma unroll
    for (int t = 0; t < 4; t++) {
#pragma unroll
        for (int h = 0; h < 2; h++) {
            const int m = row0 + m_base + t * 16 + gid + h * 8;
            const int grp = ix[m];
#pragma unroll
            for (int nt = 0; nt < 4; nt++) {
                const int cg = n0g + n_base + nt * 8 + 2 * tig;
                const int cw = cg & 511;
                float v0 = acc[t][nt][2 * h]     + bias[cw];
                float v1 = acc[t][nt][2 * h + 1] + bias[cw + 1];
                if (IS_G) {
                    v0 = expf(v0);
                    v1 = expf(v1);
                    *(float2*)&g_eg[(size_t)m * C_DIM + cw] = make_float2(v0, v1);
                    float* dp = &g_denom[(size_t)grp * C_DIM + cw];
                    atomicAdd(dp,     v0);
                    atomicAdd(dp + 1, v1);
                } else {
                    float2 e = *(const float2*)&g_eg[(size_t)m * C_DIM + cw];
                    float2 d = *(const float2*)&g_denom[(size_t)grp * C_DIM + cw];
                    float* yp = &g_y[(size_t)grp * C_DIM + cw];
                    atomicAdd(yp,     v0 * (e.x / d.x));
                    atomicAdd(yp + 1, v1 * (e.y / d.y));
                }
            }
        }
    }
}

// ---------------- yh = y @ Wh + bh (fp32 SIMT, small) ----------------
__global__ __launch_bounds__(256, 2)
void gemm_h_kernel(const float* __restrict__ Wh, const float* __restrict__ bh)
{
    constexpr int BM = 128, BN = 128, BK = 16;
    __shared__ float As[BK][BM];
    __shared__ float Bs[BK][BN];

    const int tid  = threadIdx.x;
    const int col0 = blockIdx.x * BN;
    const int row0 = blockIdx.y * BM;
    const int ty = tid >> 4, tx = tid & 15;
    const int trow = ty * 8, tcol = tx * 8;

    float acc[8][8];
#pragma unroll
    for (int i = 0; i < 8; i++)
#pragma unroll
        for (int j = 0; j < 8; j++) acc[i][j] = 0.f;

    for (int k0 = 0; k0 < C_DIM; k0 += BK) {
#pragma unroll
        for (int s = 0; s < 2; s++) {
            int ll = tid + s * 256;
            int ar  = ll >> 2;
            int akq = (ll & 3) * 4;
            float4 av = *(const float4*)&g_y[(size_t)(row0 + ar) * C_DIM + k0 + akq];
            As[akq + 0][ar] = av.x;
            As[akq + 1][ar] = av.y;
            As[akq + 2][ar] = av.z;
            As[akq + 3][ar] = av.w;
            int bk  = ll >> 5;
            int bcq = (ll & 31) * 4;
            float4 bv = *(const float4*)&Wh[(size_t)(k0 + bk) * C_DIM + col0 + bcq];
            *(float4*)&Bs[bk][bcq] = bv;
        }
        __syncthreads();
#pragma unroll
        for (int k = 0; k < BK; k++) {
            float a[8], b[8];
#pragma unroll
            for (int i = 0; i < 8; i++) a[i] = As[k][trow + i];
#pragma unroll
            for (int j = 0; j < 8; j++) b[j] = Bs[k][tcol + j];
#pragma unroll
            for (int i = 0; i < 8; i++)
#pragma unroll
                for (int j = 0; j < 8; j++)
                    acc[i][j] = fmaf(a[i], b[j], acc[i][j]);
        }
        __syncthreads();
    }

    float bv[8];
#pragma unroll
    for (int j = 0; j < 8; j++) bv[j] = bh[col0 + tcol + j];
#pragma unroll
    for (int i = 0; i < 8; i++) {
        size_t off = (size_t)(row0 + trow + i) * C_DIM + col0 + tcol;
        *(float4*)&g_yh[off]     = make_float4(acc[i][0] + bv[0], acc[i][1] + bv[1],
                                               acc[i][2] + bv[2], acc[i][3] + bv[3]);
        *(float4*)&g_yh[off + 4] = make_float4(acc[i][4] + bv[4], acc[i][5] + bv[5],
                                               acc[i][6] + bv[6], acc[i][7] + bv[7]);
    }
}

// ---------------- out[n] = yh[ix[n]] ----------------
__global__ void gather_kernel(const int* __restrict__ ix, float* __restrict__ out) {
    size_t idx = (size_t)blockIdx.x * blockDim.x + threadIdx.x;  // N*C/4
    int n  = (int)(idx >> 7);
    int cq = (int)(idx & 127) << 2;
    int g  = ix[n];
    *(float4*)&out[((size_t)n << 9) + cq] = *(const float4*)&g_yh[((size_t)g << 9) + cq];
}

extern "C" void kernel_launch(void* const* d_in, const int* in_sizes, int n_in,
                              void* d_out, int out_size) {
    const float* x  = (const float*)d_in[0];
    const int*   ix = (const int*)d_in[1];
    const float* Wf = (const float*)d_in[2];
    const float* bf = (const float*)d_in[3];
    const float* Wg = (const float*)d_in[4];
    const float* bg = (const float*)d_in[5];
    const float* Wh = (const float*)d_in[6];
    const float* bh = (const float*)d_in[7];
    float* out = (float*)d_out;

    const int SMEM = 2 * 4 * TILE_E * 2;   // 81920 bytes
    cudaFuncSetAttribute(gemm_half<true>,  cudaFuncAttributeMaxDynamicSharedMemorySize, SMEM);
    cudaFuncSetAttribute(gemm_half<false>, cudaFuncAttributeMaxDynamicSharedMemorySize, SMEM);

    zero_kernel<<<(G_DIM * C_DIM / 4) / 256, 256>>>();
    build_w_kernel<<<(NOUT * C_DIM) / 256, 256>>>(Wf, Wg);

    dim3 g1(4, N_ELEM / 128);
    gemm_half<true><<<g1, 256, SMEM>>>(x, ix, bg);    // eg + denom
    gemm_half<false><<<g1, 256, SMEM>>>(x, ix, bf);   // fx, fused aggregation

    dim3 g2(C_DIM / 128, G_DIM / 128);
    gemm_h_kernel<<<g2, 256>>>(Wh, bh);

    gather_kernel<<<(N_ELEM * (C_DIM / 4)) / 256, 256>>>(ix, out);
}